// round 4
// baseline (speedup 1.0000x reference)
#include <cuda_runtime.h>
#include <math.h>

// Problem constants
#define Bc   16
#define Tc   16
#define Hc   161
#define Wc   181
#define Cc   3
#define Fc   21
#define F4c  84
#define CINc 24
#define HWc  (Hc*Wc)            // 29141

// Tiling
#define TW   32
#define TH   8
#define HLW  (TW+2)             // 34
#define HLH  (TH+2)             // 10
#define TILE_ELEMS (CINc*HLH*HLW)   // 8160
// Weights gate-major: [tap][cin][24 co][4 gates]; co 21..23 zero pad
#define NCO  24
#define WROW (NCO*4)                // 96
#define WSZ  (9*CINc*WROW)          // 20736
#define SMEM_FLOATS (TILE_ELEMS + WSZ + WROW)
#define SMEM_BYTES  (SMEM_FLOATS*4) // 115,968 B

#define NTHR 512
#define COPT 6                      // couts per thread (4 groups x 6)

typedef unsigned long long ull;

// Persistent device state
__device__ float g_Wpack[WSZ];
__device__ float g_h0[Bc*Fc*HWc];
__device__ float g_h1[Bc*Fc*HWc];
__device__ float g_c [Bc*Fc*HWc];

__device__ __forceinline__ float hsig(float v) {
    return fminf(fmaxf(0.2f*v + 0.5f, 0.0f), 1.0f);
}

// ---------------------------------------------------------------------------
__global__ void pack_kernel(const float* __restrict__ k, const float* __restrict__ rk) {
    int i = blockIdx.x*blockDim.x + threadIdx.x;
    if (i >= WSZ) return;
    int kk  = i / (CINc*WROW);
    int r   = i - kk*(CINc*WROW);
    int cin = r / WROW;
    int q   = r - cin*WROW;
    int co  = q >> 2;
    int g   = q & 3;
    float v = 0.0f;
    if (co < Fc) {
        int col = g*Fc + co;
        if (cin < Cc) v = k [(kk*Cc + cin)*F4c + col];
        else          v = rk[(kk*Fc + (cin-Cc))*F4c + col];
    }
    g_Wpack[i] = v;
}

__global__ void zero_kernel() {
    const int n = Bc*Fc*HWc;
    for (int i = blockIdx.x*blockDim.x + threadIdx.x; i < n; i += gridDim.x*blockDim.x) {
        g_h0[i] = 0.0f;
        g_c [i] = 0.0f;
    }
}

// ---------------------------------------------------------------------------
// One ConvLSTM timestep. 512 thr = 4 cogroups x 128; each thread does
// 2 vertically-adjacent pixels x 6 couts x 4 gates (FFMA2 over gate pairs).
// ---------------------------------------------------------------------------
__global__ __launch_bounds__(NTHR, 1)
void step_kernel(const float* __restrict__ x, const float* __restrict__ bias,
                 int t, int dir) {
    extern __shared__ float sm[];
    float* s_tile = sm;                     // [CIN][HLH][HLW]
    float* s_W    = sm + TILE_ELEMS;        // [9*CIN][96]
    float* s_bias = s_W + WSZ;              // [96] gate-major packed

    const float* h_in  = dir ? g_h1 : g_h0;
    float*       h_out = dir ? g_h0 : g_h1;

    const int tid = threadIdx.x;
    const int bx = blockIdx.x, by = blockIdx.y, b = blockIdx.z;
    const int x0 = bx*TW, y0 = by*TH;

    // Stage weights (vectorized) + packed bias
    {
        const float4* gw4 = reinterpret_cast<const float4*>(g_Wpack);
        float4*       sw4 = reinterpret_cast<float4*>(s_W);
        #pragma unroll 4
        for (int i = tid; i < WSZ/4; i += NTHR) sw4[i] = gw4[i];
        if (tid < WROW) {
            int co = tid >> 2, g = tid & 3;
            s_bias[tid] = (co < Fc) ? bias[g*Fc + co] : 0.0f;
        }
    }

    // Stage halo tile: ch 0..2 = x_t, ch 3..23 = h_in; zero-pad OOB
    for (int i = tid; i < TILE_ELEMS; i += NTHR) {
        int cin = i / (HLH*HLW);
        int r   = i - cin*(HLH*HLW);
        int row = r / HLW;
        int col = r - row*HLW;
        int gy = y0 + row - 1;
        int gx = x0 + col - 1;
        float v = 0.0f;
        if ((unsigned)gy < (unsigned)Hc && (unsigned)gx < (unsigned)Wc) {
            if (cin < Cc)
                v = x[(((size_t)(b*Tc + t)*Hc + gy)*Wc + gx)*Cc + cin];
            else
                v = h_in[((size_t)(b*Fc + (cin - Cc)))*HWc + (size_t)gy*Wc + gx];
        }
        s_tile[i] = v;
    }
    __syncthreads();

    const int group = tid >> 7;          // 0..3 -> co [6g, 6g+6)
    const int rr    = tid & 127;
    const int tx    = rr & 31;
    const int row2  = (rr >> 5) * 2;     // 0,2,4,6
    const int cobase = group * COPT;

    // Accumulators: 2 px x 6 co x 2 pairs ({i,f},{g,o}) = 24 ull = 48 regs
    ull acc0[2*COPT], acc1[2*COPT];
    {
        const ull* b2 = reinterpret_cast<const ull*>(s_bias + cobase*4);
        #pragma unroll
        for (int j = 0; j < 2*COPT; j++) { acc0[j] = b2[j]; acc1[j] = b2[j]; }
    }

    // Mainloop: per (cin,tap): 6 LDS.128 weights + 2 data LDS, 24 FFMA2
    #pragma unroll 1
    for (int cin = 0; cin < CINc; cin++) {
        const float* tp = s_tile + cin*(HLH*HLW) + row2*HLW + tx;
        #pragma unroll
        for (int kk = 0; kk < 9; kk++) {
            const int dy = kk/3, dx = kk - 3*(kk/3);
            const float da = tp[dy*HLW + dx];
            const float db = tp[(dy+1)*HLW + dx];
            ull d2a, d2b;
            asm("mov.b64 %0, {%1, %1};" : "=l"(d2a) : "f"(da));
            asm("mov.b64 %0, {%1, %1};" : "=l"(d2b) : "f"(db));
            const ulonglong2* w = reinterpret_cast<const ulonglong2*>(
                s_W + (kk*CINc + cin)*WROW + cobase*4);
            #pragma unroll
            for (int j = 0; j < COPT; j++) {
                ulonglong2 wv = w[j];
                asm("fma.rn.f32x2 %0, %1, %2, %0;" : "+l"(acc0[2*j  ]) : "l"(d2a), "l"(wv.x));
                asm("fma.rn.f32x2 %0, %1, %2, %0;" : "+l"(acc0[2*j+1]) : "l"(d2a), "l"(wv.y));
                asm("fma.rn.f32x2 %0, %1, %2, %0;" : "+l"(acc1[2*j  ]) : "l"(d2b), "l"(wv.x));
                asm("fma.rn.f32x2 %0, %1, %2, %0;" : "+l"(acc1[2*j+1]) : "l"(d2b), "l"(wv.y));
            }
        }
    }

    // Gate epilogue: each thread owns full (i,f,g,o) per co, both pixels
    const int ox = x0 + tx;
    #pragma unroll
    for (int px = 0; px < 2; px++) {
        const int oy = y0 + row2 + px;
        if (ox < Wc && oy < Hc) {
            const ull* ac = px ? acc1 : acc0;
            const size_t p = (size_t)oy*Wc + ox;
            #pragma unroll
            for (int j = 0; j < COPT; j++) {
                const int co = cobase + j;
                if (co < Fc) {
                    float zi, zf, zg, zo;
                    asm("mov.b64 {%0, %1}, %2;" : "=f"(zi), "=f"(zf) : "l"(ac[2*j  ]));
                    asm("mov.b64 {%0, %1}, %2;" : "=f"(zg), "=f"(zo) : "l"(ac[2*j+1]));
                    float ig = hsig(zi);
                    float fg = hsig(zf);
                    float gg = tanhf(zg);
                    float og = hsig(zo);
                    size_t idx = ((size_t)(b*Fc + co))*HWc + p;
                    float cn = fg * g_c[idx] + ig * gg;
                    g_c[idx] = cn;
                    h_out[idx] = og * tanhf(cn);
                }
            }
        }
    }
}

// ---------------------------------------------------------------------------
__global__ void mask_out_kernel(const float* __restrict__ mask, float* __restrict__ out) {
    const int n = Bc*HWc*Fc;
    int i = blockIdx.x*blockDim.x + threadIdx.x;
    if (i >= n) return;
    int co   = i % Fc;
    int rest = i / Fc;
    int p    = rest % HWc;
    int b    = rest / HWc;
    out[i] = g_h0[((size_t)(b*Fc + co))*HWc + p] * mask[p];
}

// ---------------------------------------------------------------------------
extern "C" void kernel_launch(void* const* d_in, const int* in_sizes, int n_in,
                              void* d_out, int out_size) {
    const float* x     = (const float*)d_in[0];
    const float* kern  = (const float*)d_in[1];
    const float* rkern = (const float*)d_in[2];
    const float* bias  = (const float*)d_in[3];
    const float* mask  = (const float*)d_in[4];
    float* out = (float*)d_out;
    (void)in_sizes; (void)n_in; (void)out_size;

    cudaFuncSetAttribute(step_kernel, cudaFuncAttributeMaxDynamicSharedMemorySize,
                         SMEM_BYTES);

    pack_kernel<<<(WSZ + 255)/256, 256>>>(kern, rkern);
    zero_kernel<<<4096, 256>>>();

    dim3 grid((Wc + TW - 1)/TW, (Hc + TH - 1)/TH, Bc);  // (6, 21, 16)
    for (int t = 0; t < Tc; t++) {
        step_kernel<<<grid, NTHR, SMEM_BYTES>>>(x, bias, t, t & 1);
    }

    const int n = Bc*HWc*Fc;
    mask_out_kernel<<<(n + 255)/256, 256>>>(mask, out);
}

// round 5
// speedup vs baseline: 1.1391x; 1.1391x over previous
#include <cuda_runtime.h>
#include <math.h>

// Problem constants
#define Bc   16
#define Tc   16
#define Hc   161
#define Wc   181
#define Cc   3
#define Fc   21
#define F4c  84
#define CINc 24
#define HWc  (Hc*Wc)            // 29141

// Tiling (R3 structure: 256 thr, 2 blocks/SM)
#define TW   32
#define TH   8
#define HLW  (TW+2)             // 34
#define HLH  (TH+2)             // 10
#define TILE_ELEMS (CINc*HLH*HLW)   // 8160

// Weight split: 22 co-slots x 4 gates. Per group (11 slots): 6 slots from
// smem, 5 from constant memory.
//   smem rows:  12 slots (48 floats)  -> co {0..5} & {11..16}
//   const rows: 10 slots (40 floats)  -> co {6..10} & {17..21(pad)}
#define SSLOT 12
#define CSLOT 10
#define WS_SZ (9*CINc*SSLOT*4)      // 10368 floats
#define WC_SZ (9*CINc*CSLOT*4)      // 8640 floats (34,560 B)
#define SMEM_FLOATS (TILE_ELEMS + WS_SZ + 88)
#define SMEM_BYTES  (SMEM_FLOATS*4) // 74,464 B -> 2 blocks/SM

typedef unsigned long long ull;

// Persistent device state
__device__ float g_Wsm[WS_SZ];
__device__ float g_Wc [WC_SZ];               // staging for const copy
__constant__ ulonglong2 c_W[9*CINc*CSLOT/1]; // [9*24][10 slots] 16B each
__device__ float g_h0[Bc*Fc*HWc];
__device__ float g_h1[Bc*Fc*HWc];
__device__ float g_c [Bc*Fc*HWc];

__device__ __forceinline__ float hsig(float v) {
    return fminf(fmaxf(0.2f*v + 0.5f, 0.0f), 1.0f);
}

// slot -> output-channel co mapping
__host__ __device__ __forceinline__ int sslot_to_co(int s) {
    return (s < 6) ? s : 11 + (s - 6);          // {0..5, 11..16}
}
__host__ __device__ __forceinline__ int cslot_to_co(int u) {
    return (u < 5) ? 6 + u : 17 + (u - 5);      // {6..10, 17..21}
}

// ---------------------------------------------------------------------------
// Pack Wx (3,3,3,84) + Wh (3,3,21,84) gate-major into split smem/const arrays.
// source col for (co, g) = g*21 + co ; co==21 -> zero pad
// ---------------------------------------------------------------------------
__global__ void pack_kernel(const float* __restrict__ k, const float* __restrict__ rk) {
    int i = blockIdx.x*blockDim.x + threadIdx.x;
    const int NS = 9*CINc*SSLOT*4;
    const int NC = 9*CINc*CSLOT*4;
    if (i < NS) {
        int kc  = i / (SSLOT*4);     // kk*24+cin
        int q   = i - kc*(SSLOT*4);
        int s   = q >> 2;
        int g   = q & 3;
        int co  = sslot_to_co(s);
        int kk  = kc / CINc, cin = kc - kk*CINc;
        float v = 0.0f;
        if (co < Fc) {
            int col = g*Fc + co;
            if (cin < Cc) v = k [(kk*Cc + cin)*F4c + col];
            else          v = rk[(kk*Fc + (cin-Cc))*F4c + col];
        }
        g_Wsm[i] = v;
    }
    int j = i - NS;
    if (j >= 0 && j < NC) {
        int kc  = j / (CSLOT*4);
        int q   = j - kc*(CSLOT*4);
        int u   = q >> 2;
        int g   = q & 3;
        int co  = cslot_to_co(u);
        int kk  = kc / CINc, cin = kc - kk*CINc;
        float v = 0.0f;
        if (co < Fc) {
            int col = g*Fc + co;
            if (cin < Cc) v = k [(kk*Cc + cin)*F4c + col];
            else          v = rk[(kk*Fc + (cin-Cc))*F4c + col];
        }
        g_Wc[j] = v;
    }
}

__global__ void zero_kernel() {
    const int n = Bc*Fc*HWc;
    for (int i = blockIdx.x*blockDim.x + threadIdx.x; i < n; i += gridDim.x*blockDim.x) {
        g_h0[i] = 0.0f;
        g_c [i] = 0.0f;
    }
}

// ---------------------------------------------------------------------------
// One ConvLSTM timestep. 256 thr = 2 cogroups x 128; each thread: 2 vertical
// pixels x 11 couts x 4 gates. Weights: 6 LDS.128 + 5 LDC.128 per iter.
// ---------------------------------------------------------------------------
__global__ __launch_bounds__(256, 2)
void step_kernel(const float* __restrict__ x, const float* __restrict__ bias,
                 int t, int dir) {
    extern __shared__ float sm[];
    float* s_tile = sm;                     // [CIN][HLH][HLW]
    float* s_W    = sm + TILE_ELEMS;        // [9*CIN][48]
    float* s_bias = s_W + WS_SZ;            // [88] gate-major by co

    const float* h_in  = dir ? g_h1 : g_h0;
    float*       h_out = dir ? g_h0 : g_h1;

    const int tid = threadIdx.x;
    const int bx = blockIdx.x, by = blockIdx.y, b = blockIdx.z;
    const int x0 = bx*TW, y0 = by*TH;

    // Stage smem weights + bias
    {
        const float4* gw4 = reinterpret_cast<const float4*>(g_Wsm);
        float4*       sw4 = reinterpret_cast<float4*>(s_W);
        #pragma unroll 4
        for (int i = tid; i < WS_SZ/4; i += 256) sw4[i] = gw4[i];
        if (tid < 88) {
            int co = tid >> 2, g = tid & 3;
            s_bias[tid] = (co < Fc) ? bias[g*Fc + co] : 0.0f;
        }
    }

    // Stage halo tile: ch 0..2 = x_t, ch 3..23 = h_in; zero-pad OOB
    for (int i = tid; i < TILE_ELEMS; i += 256) {
        int cin = i / (HLH*HLW);
        int r   = i - cin*(HLH*HLW);
        int row = r / HLW;
        int col = r - row*HLW;
        int gy = y0 + row - 1;
        int gx = x0 + col - 1;
        float v = 0.0f;
        if ((unsigned)gy < (unsigned)Hc && (unsigned)gx < (unsigned)Wc) {
            if (cin < Cc)
                v = x[(((size_t)(b*Tc + t)*Hc + gy)*Wc + gx)*Cc + cin];
            else
                v = h_in[((size_t)(b*Fc + (cin - Cc)))*HWc + (size_t)gy*Wc + gx];
        }
        s_tile[i] = v;
    }
    __syncthreads();

    const int group = tid >> 7;          // 0: co 0..10, 1: co 11..21(pad)
    const int rr    = tid & 127;
    const int tx    = rr & 31;
    const int row2  = (rr >> 5) * 2;     // 0,2,4,6
    const int cobase = group * 11;

    // Accumulators: 2 px x 11 co x 2 pairs = 44 ull (88 regs)
    ull acc0[22], acc1[22];
    {
        const ull* b2 = reinterpret_cast<const ull*>(s_bias + cobase*4);
        #pragma unroll
        for (int j = 0; j < 22; j++) { acc0[j] = b2[j]; acc1[j] = b2[j]; }
    }

    const int soff = group*6;            // smem slot base for this group
    const int coff = group*5;            // const slot base

    // Mainloop: per (cin,tap): 2 LDS.32 data + 6 LDS.128 + 5 LDC.128, 44 FFMA2
    #pragma unroll 1
    for (int cin = 0; cin < CINc; cin++) {
        const float* tp = s_tile + cin*(HLH*HLW) + row2*HLW + tx;
        #pragma unroll
        for (int kk = 0; kk < 9; kk++) {
            const int dy = kk/3, dx = kk - 3*(kk/3);
            const float da = tp[dy*HLW + dx];
            const float db = tp[(dy+1)*HLW + dx];
            ull d2a, d2b;
            asm("mov.b64 %0, {%1, %1};" : "=l"(d2a) : "f"(da));
            asm("mov.b64 %0, {%1, %1};" : "=l"(d2b) : "f"(db));
            const ulonglong2* ws = reinterpret_cast<const ulonglong2*>(
                s_W + (kk*CINc + cin)*(SSLOT*4)) + soff;
            const ulonglong2* wc = &c_W[(kk*CINc + cin)*CSLOT + coff];
            // smem-sourced slots -> co cobase+0..5
            #pragma unroll
            for (int j = 0; j < 6; j++) {
                ulonglong2 wv = ws[j];
                asm("fma.rn.f32x2 %0, %1, %2, %0;" : "+l"(acc0[2*j  ]) : "l"(d2a), "l"(wv.x));
                asm("fma.rn.f32x2 %0, %1, %2, %0;" : "+l"(acc0[2*j+1]) : "l"(d2a), "l"(wv.y));
                asm("fma.rn.f32x2 %0, %1, %2, %0;" : "+l"(acc1[2*j  ]) : "l"(d2b), "l"(wv.x));
                asm("fma.rn.f32x2 %0, %1, %2, %0;" : "+l"(acc1[2*j+1]) : "l"(d2b), "l"(wv.y));
            }
            // const-sourced slots -> co cobase+6..10
            #pragma unroll
            for (int u = 0; u < 5; u++) {
                ulonglong2 wv = wc[u];
                const int j = 6 + u;
                asm("fma.rn.f32x2 %0, %1, %2, %0;" : "+l"(acc0[2*j  ]) : "l"(d2a), "l"(wv.x));
                asm("fma.rn.f32x2 %0, %1, %2, %0;" : "+l"(acc0[2*j+1]) : "l"(d2a), "l"(wv.y));
                asm("fma.rn.f32x2 %0, %1, %2, %0;" : "+l"(acc1[2*j  ]) : "l"(d2b), "l"(wv.x));
                asm("fma.rn.f32x2 %0, %1, %2, %0;" : "+l"(acc1[2*j+1]) : "l"(d2b), "l"(wv.y));
            }
        }
    }

    // Gate epilogue: thread owns full (i,f,g,o) per co, both pixels
    const int ox = x0 + tx;
    #pragma unroll
    for (int px = 0; px < 2; px++) {
        const int oy = y0 + row2 + px;
        if (ox < Wc && oy < Hc) {
            const ull* ac = px ? acc1 : acc0;
            const size_t p = (size_t)oy*Wc + ox;
            #pragma unroll
            for (int j = 0; j < 11; j++) {
                const int co = cobase + j;
                if (co < Fc) {
                    float zi, zf, zg, zo;
                    asm("mov.b64 {%0, %1}, %2;" : "=f"(zi), "=f"(zf) : "l"(ac[2*j  ]));
                    asm("mov.b64 {%0, %1}, %2;" : "=f"(zg), "=f"(zo) : "l"(ac[2*j+1]));
                    float ig = hsig(zi);
                    float fg = hsig(zf);
                    float gg = tanhf(zg);
                    float og = hsig(zo);
                    size_t idx = ((size_t)(b*Fc + co))*HWc + p;
                    float cn = fg * g_c[idx] + ig * gg;
                    g_c[idx] = cn;
                    h_out[idx] = og * tanhf(cn);
                }
            }
        }
    }
}

// ---------------------------------------------------------------------------
__global__ void mask_out_kernel(const float* __restrict__ mask, float* __restrict__ out) {
    const int n = Bc*HWc*Fc;
    int i = blockIdx.x*blockDim.x + threadIdx.x;
    if (i >= n) return;
    int co   = i % Fc;
    int rest = i / Fc;
    int p    = rest % HWc;
    int b    = rest / HWc;
    out[i] = g_h0[((size_t)(b*Fc + co))*HWc + p] * mask[p];
}

// ---------------------------------------------------------------------------
extern "C" void kernel_launch(void* const* d_in, const int* in_sizes, int n_in,
                              void* d_out, int out_size) {
    const float* x     = (const float*)d_in[0];
    const float* kern  = (const float*)d_in[1];
    const float* rkern = (const float*)d_in[2];
    const float* bias  = (const float*)d_in[3];
    const float* mask  = (const float*)d_in[4];
    float* out = (float*)d_out;
    (void)in_sizes; (void)n_in; (void)out_size;

    cudaFuncSetAttribute(step_kernel, cudaFuncAttributeMaxDynamicSharedMemorySize,
                         SMEM_BYTES);

    pack_kernel<<<(WS_SZ + WC_SZ + 255)/256, 256>>>(kern, rkern);
    zero_kernel<<<4096, 256>>>();

    // Copy packed const-side weights into __constant__ (graph-legal D2D copy)
    void *dst = nullptr, *src = nullptr;
    cudaGetSymbolAddress(&dst, c_W);
    cudaGetSymbolAddress(&src, g_Wc);
    cudaMemcpyAsync(dst, src, WC_SZ*sizeof(float), cudaMemcpyDeviceToDevice, 0);

    dim3 grid((Wc + TW - 1)/TW, (Hc + TH - 1)/TH, Bc);  // (6, 21, 16)
    for (int t = 0; t < Tc; t++) {
        step_kernel<<<grid, 256, SMEM_BYTES>>>(x, bias, t, t & 1);
    }

    const int n = Bc*HWc*Fc;
    mask_out_kernel<<<(n + 255)/256, 256>>>(mask, out);
}

// round 7
// speedup vs baseline: 1.2054x; 1.0582x over previous
#include <cuda_runtime.h>
#include <cuda_bf16.h>
#include <math.h>
#include <cstdint>

// ===========================================================================
// Problem constants
// ===========================================================================
#define Bc   16
#define Tc   16
#define Hc   161
#define Wc   181
#define HWc  (Hc*Wc)            // 29141
#define Fc   21
#define F4c  84

// Tile: M = 384 pixels (96 wide x 4 high), N = 88 (n = 4*co+g), K = 3x240
#define TILE_W 96
#define TILE_H 4

// B matrix: n-major [88][248] bf16 per precision (row 496 B, k 240..247 pad=0)
#define BROW   248
#define BPLANE_B (88*BROW*2)        // 43,648
#define B_TOTAL_B (2*BPLANE_B)      // 87,296

// Halo: channel-last [6 rows][98 cols][24 ch] bf16, 2 precisions
#define HROWS 6
#define HCOLS 98
#define HCH   24
#define HPLANE_B (HROWS*HCOLS*HCH*2)   // 28,224

// SMEM layout
#define SM_B     0
#define SM_HALO  B_TOTAL_B                      // 87,296
#define SM_BIAS  (SM_HALO + 2*HPLANE_B + 32)    // 143,776 (32B zero pad tail)
#define SMEM_BYTES (SM_BIAS + 352)              // 144,128

#define HSZ (Bc*Fc*HWc)
#define XSZ (Bc*Tc*3*HWc)

// ===========================================================================
// Device globals
// ===========================================================================
__device__ __nv_bfloat16 g_B[2*88*BROW];        // packed weights hi/lo
__device__ __nv_bfloat16 g_hh0[HSZ], g_hl0[HSZ];
__device__ __nv_bfloat16 g_hh1[HSZ], g_hl1[HSZ];
__device__ float         g_c[HSZ];
__device__ __nv_bfloat16 g_xh[XSZ], g_xl[XSZ];

// ===========================================================================
// PTX helpers (compute_103-safe: ldmatrix + mma.sync only)
// ===========================================================================
__device__ __forceinline__ uint32_t smem_to_u32(const void* p) {
    uint32_t a;
    asm("{ .reg .u64 t; cvta.to.shared.u64 t, %1; cvt.u32.u64 %0, t; }"
        : "=r"(a) : "l"(p));
    return a;
}
#define LDSM_X4(r0,r1,r2,r3,addr) \
    asm volatile("ldmatrix.sync.aligned.m8n8.x4.shared.b16 {%0,%1,%2,%3}, [%4];" \
        : "=r"(r0),"=r"(r1),"=r"(r2),"=r"(r3) : "r"(addr))
#define LDSM_X2(r0,r1,addr) \
    asm volatile("ldmatrix.sync.aligned.m8n8.x2.shared.b16 {%0,%1}, [%2];" \
        : "=r"(r0),"=r"(r1) : "r"(addr))
#define MMA16816(d,a0,a1,a2,a3,b0,b1) \
    asm volatile("mma.sync.aligned.m16n8k16.row.col.f32.bf16.bf16.f32 " \
        "{%0,%1,%2,%3}, {%4,%5,%6,%7}, {%8,%9}, {%0,%1,%2,%3};" \
        : "+f"((d)[0]),"+f"((d)[1]),"+f"((d)[2]),"+f"((d)[3]) \
        : "r"(a0),"r"(a1),"r"(a2),"r"(a3),"r"(b0),"r"(b1))

__device__ __forceinline__ float hsig(float v) {
    return fminf(fmaxf(0.2f*v + 0.5f, 0.0f), 1.0f);
}

// ===========================================================================
// Aux kernels
// ===========================================================================
__global__ void zero_kernel() {
    for (int i = blockIdx.x*blockDim.x + threadIdx.x; i < HSZ; i += gridDim.x*blockDim.x) {
        g_c[i] = 0.0f;
        g_hh0[i] = __float2bfloat16(0.0f);
        g_hl0[i] = __float2bfloat16(0.0f);
    }
}

// x -> planar bf16 hi/lo: plane ((b*T+t)*3+c), idx [HW]
__global__ void xsplit_kernel(const float* __restrict__ x) {
    for (int i = blockIdx.x*blockDim.x + threadIdx.x; i < XSZ; i += gridDim.x*blockDim.x) {
        int p  = i % HWc;
        int r  = i / HWc;
        int c  = r % 3;
        int bt = r / 3;
        float v = x[((size_t)bt*HWc + p)*3 + c];
        __nv_bfloat16 hi = __float2bfloat16(v);
        g_xh[i] = hi;
        g_xl[i] = __float2bfloat16(v - __bfloat162float(hi));
    }
}

// Pack weights: B[prec][n][k], n = 4*co+g, k = dy*80 + dx*24 + cin
// (k%80 >= 72 and k >= 240 are zero pad; co >= 21 zero)
__global__ void packB_kernel(const float* __restrict__ kern, const float* __restrict__ rkern) {
    int i = blockIdx.x*blockDim.x + threadIdx.x;
    const int TOT = 2*88*BROW;
    if (i >= TOT) return;
    int prec = i / (88*BROW);
    int r    = i - prec*(88*BROW);
    int n    = r / BROW;
    int k    = r - n*BROW;
    int co = n >> 2, g = n & 3;
    float w = 0.0f;
    if (k < 240 && co < Fc) {
        int dy = k / 80, r2 = k - dy*80;
        if (r2 < 72) {
            int dx = r2 / 24, cin = r2 - dx*24;
            int col = g*Fc + co;
            if (cin < 3) w = kern [((dy*3 + dx)*3  + cin    )*F4c + col];
            else         w = rkern[((dy*3 + dx)*Fc + (cin-3))*F4c + col];
        }
    }
    __nv_bfloat16 hi = __float2bfloat16(w);
    g_B[i] = prec ? __float2bfloat16(w - __bfloat162float(hi)) : hi;
}

// ===========================================================================
// One ConvLSTM timestep: bf16x3 HMMA GEMM (M=384, N=88, K=3x240)
// ===========================================================================
__global__ __launch_bounds__(256, 1)
void step_kernel(const float* __restrict__ bias, int t) {
    extern __shared__ unsigned char smem[];
    const uint32_t sbase = smem_to_u32(smem);
    const int tid  = threadIdx.x;
    const int w    = tid >> 5;
    const int lane = tid & 31;
    const int b  = blockIdx.z;
    const int x0 = blockIdx.x * TILE_W;
    const int y0 = blockIdx.y * TILE_H;

    const __nv_bfloat16* hh_in = (t & 1) ? g_hh1 : g_hh0;
    const __nv_bfloat16* hl_in = (t & 1) ? g_hl1 : g_hl0;
    __nv_bfloat16* hh_out = (t & 1) ? g_hh0 : g_hh1;
    __nv_bfloat16* hl_out = (t & 1) ? g_hl0 : g_hl1;

    // ---- Stage B (flat copy, pre-packed n-major hi/lo) ----
    {
        const float4* gB = reinterpret_cast<const float4*>(g_B);
        float4* sB = reinterpret_cast<float4*>(smem + SM_B);
        #pragma unroll 4
        for (int i = tid; i < B_TOTAL_B/16; i += 256) sB[i] = gB[i];
    }
    // ---- Bias (n = 4co+g) ----
    if (tid < 88) {
        int co = tid >> 2, g = tid & 3;
        reinterpret_cast<float*>(smem + SM_BIAS)[tid] = (co < Fc) ? bias[g*Fc + co] : 0.0f;
    }
    // ---- Halo staging: [prec][r][c][ch] channel-last, 4B (ch-pair) stores ----
    {
        const int HTOT = 2*HROWS*(HCH/2)*HCOLS;   // 14,112 pair-stores
        for (int i = tid; i < HTOT; i += 256) {
            int c   = i % HCOLS;
            int chp = (i / HCOLS) % (HCH/2);
            int r   = (i / (HCOLS*(HCH/2))) % HROWS;
            int p   = i / (HCOLS*(HCH/2)*HROWS);
            int gy = y0 + r - 1, gx = x0 + c - 1;
            __nv_bfloat162 v;
            v.x = __float2bfloat16(0.0f); v.y = v.x;
            if ((unsigned)gy < (unsigned)Hc && (unsigned)gx < (unsigned)Wc) {
                size_t pix = (size_t)gy*Wc + gx;
                #pragma unroll
                for (int q = 0; q < 2; q++) {
                    int ch = 2*chp + q;
                    __nv_bfloat16 val;
                    if (ch < 3) {
                        const __nv_bfloat16* pl = (p ? g_xl : g_xh)
                            + ((size_t)((b*Tc + t)*3 + ch))*HWc;
                        val = pl[pix];
                    } else {
                        const __nv_bfloat16* pl = (p ? hl_in : hh_in)
                            + ((size_t)(b*Fc + (ch - 3)))*HWc;
                        val = pl[pix];
                    }
                    if (q == 0) v.x = val; else v.y = val;
                }
            }
            *reinterpret_cast<__nv_bfloat162*>(
                smem + SM_HALO + (size_t)p*HPLANE_B
                + ((size_t)(r*HCOLS + c)*HCH + 2*chp)*2) = v;
        }
        // zero 32B pad tail after plane 1 (A k-pad overreads land here)
        if (tid < 8)
            reinterpret_cast<uint32_t*>(smem + SM_HALO + 2*HPLANE_B)[tid] = 0;
    }
    __syncthreads();

    // ---- Warp tile: m48 (3 m16 frags) x n88 (11 n8 frags) ----
    const int my  = w >> 1;             // pixel row in tile (0..3)
    const int mxb = 48*(w & 1);         // pixel col base (0 or 48)

    float d[3][11][4];
    #pragma unroll
    for (int mf = 0; mf < 3; mf++)
        #pragma unroll
        for (int nf = 0; nf < 11; nf++)
            #pragma unroll
            for (int q = 0; q < 4; q++) d[mf][nf][q] = 0.0f;

    // ldmatrix lane addressing components
    const uint32_t aLane = (uint32_t)(lane & 15)*48 + (uint32_t)((lane >> 4) & 1)*16;
    const uint32_t bLane = (uint32_t)(lane & 7)*496 + (uint32_t)((lane >> 3) & 1)*16;

    // 3 compensation passes: (Ah,Bh), (Al,Bh), (Ah,Bl)
    #pragma unroll 1
    for (int ps = 0; ps < 3; ps++) {
        const uint32_t Ab = sbase + SM_HALO + ((ps == 1) ? HPLANE_B : 0);
        const uint32_t Bb = sbase + SM_B + ((ps == 2) ? BPLANE_B : 0) + bLane;
        #pragma unroll 1
        for (int dy = 0; dy < 3; dy++) {
            const uint32_t Arow = Ab + (uint32_t)((my + dy)*HCOLS + mxb)*48 + aLane;
            const uint32_t Brow = Bb + (uint32_t)dy*160;
            #pragma unroll
            for (int c = 0; c < 5; c++) {
                uint32_t bq[22];
                #pragma unroll
                for (int nf = 0; nf < 11; nf++)
                    LDSM_X2(bq[2*nf], bq[2*nf+1], Brow + nf*(8*496) + c*32);
                #pragma unroll
                for (int mf = 0; mf < 3; mf++) {
                    uint32_t a0, a1, a2, a3;
                    LDSM_X4(a0, a1, a2, a3, Arow + mf*(16*48) + c*32);
                    #pragma unroll
                    for (int nf = 0; nf < 11; nf++)
                        MMA16816(d[mf][nf], a0, a1, a2, a3, bq[2*nf], bq[2*nf+1]);
                }
            }
        }
    }

    // ---- Epilogue: shfl_xor(1) gate exchange, per-lane (pixel, co) update ----
    const int gid    = lane >> 2;
    const int co_off = (lane >> 1) & 1;
    const bool lowrow = ((lane & 1) == 0);
    const int gy = y0 + my;
    const float* sb_all = reinterpret_cast<const float*>(smem + SM_BIAS);

    #pragma unroll
    for (int mf = 0; mf < 3; mf++) {
        #pragma unroll
        for (int nf = 0; nf < 11; nf++) {
            float* dd = d[mf][nf];
            float r0 = __shfl_xor_sync(0xFFFFFFFFu, dd[0], 1);
            float r1 = __shfl_xor_sync(0xFFFFFFFFu, dd[1], 1);
            float r2 = __shfl_xor_sync(0xFFFFFFFFu, dd[2], 1);
            float r3 = __shfl_xor_sync(0xFFFFFFFFu, dd[3], 1);
            float zi, zf, zg, zo;
            int rowm;
            if (lowrow) { zi = dd[0]; zf = dd[1]; zg = r0;    zo = r1;    rowm = gid; }
            else        { zi = r2;    zf = r3;    zg = dd[2]; zo = dd[3]; rowm = gid + 8; }
            const int co = 2*nf + co_off;
            const int gx = x0 + mxb + mf*16 + rowm;
            if (co < Fc && gx < Wc && gy < Hc) {
                const float* sb = sb_all + co*4;
                float ig = hsig(zi + sb[0]);
                float fg = hsig(zf + sb[1]);
                float gg = tanhf(zg + sb[2]);
                float og = hsig(zo + sb[3]);
                size_t idx = ((size_t)(b*Fc + co))*HWc + (size_t)gy*Wc + gx;
                float cn = fg * g_c[idx] + ig * gg;
                g_c[idx] = cn;
                float h = og * tanhf(cn);
                __nv_bfloat16 hh = __float2bfloat16(h);
                hh_out[idx] = hh;
                hl_out[idx] = __float2bfloat16(h - __bfloat162float(hh));
            }
        }
    }
}

// ===========================================================================
// out[b,h,w,co] = (h_hi + h_lo)[b,co,h,w] * mask[h,w]
// ===========================================================================
__global__ void mask_out_kernel(const float* __restrict__ mask, float* __restrict__ out) {
    const int n = Bc*HWc*Fc;
    int i = blockIdx.x*blockDim.x + threadIdx.x;
    if (i >= n) return;
    int co   = i % Fc;
    int rest = i / Fc;
    int p    = rest % HWc;
    int b    = rest / HWc;
    size_t idx = ((size_t)(b*Fc + co))*HWc + p;
    float h = __bfloat162float(g_hh0[idx]) + __bfloat162float(g_hl0[idx]);
    out[i] = h * mask[p];
}

// ===========================================================================
extern "C" void kernel_launch(void* const* d_in, const int* in_sizes, int n_in,
                              void* d_out, int out_size) {
    const float* x     = (const float*)d_in[0];
    const float* kern  = (const float*)d_in[1];
    const float* rkern = (const float*)d_in[2];
    const float* bias  = (const float*)d_in[3];
    const float* mask  = (const float*)d_in[4];
    float* out = (float*)d_out;
    (void)in_sizes; (void)n_in; (void)out_size;

    cudaFuncSetAttribute(step_kernel, cudaFuncAttributeMaxDynamicSharedMemorySize,
                         SMEM_BYTES);

    zero_kernel<<<2048, 256>>>();
    xsplit_kernel<<<4096, 256>>>(x);
    packB_kernel<<<(2*88*BROW + 255)/256, 256>>>(kern, rkern);

    dim3 grid((Wc + TILE_W - 1)/TILE_W, (Hc + TILE_H - 1)/TILE_H, Bc); // (2,41,16)
    for (int t = 0; t < Tc; t++) {
        step_kernel<<<grid, 256, SMEM_BYTES>>>(bias, t);
    }

    const int n = Bc*HWc*Fc;
    mask_out_kernel<<<(n + 255)/256, 256>>>(mask, out);
}

// round 8
// speedup vs baseline: 1.7255x; 1.4315x over previous
#include <cuda_runtime.h>
#include <cuda_bf16.h>
#include <math.h>
#include <cstdint>

// ===========================================================================
// Problem constants
// ===========================================================================
#define Bc   16
#define Tc   16
#define Hc   161
#define Wc   181
#define HWc  (Hc*Wc)            // 29141
#define Fc   21
#define F4c  84

// Tile: M = 384 pixels (96 wide x 4 high), N = 88 (n = 4*co+g), K = 3x240
// 16 warps: warp = m48 x n44 (nhalf 0: nf=6 / nhalf 1: nf=5)
#define TILE_W 96
#define TILE_H 4

// B matrix: n-major [88][248] bf16 per precision (row 496 B, k 240..247 pad=0)
#define BROW   248
#define BPLANE_B (88*BROW*2)        // 43,648
#define B_TOTAL_B (2*BPLANE_B)      // 87,296

// Halo: channel-last [6 rows][98 cols][24 ch] bf16, 2 precisions
#define HROWS 6
#define HCOLS 98
#define HCH   24
#define HPLANE_B (HROWS*HCOLS*HCH*2)   // 28,224

// SMEM layout
#define SM_B     0
#define SM_HALO  B_TOTAL_B                      // 87,296
#define SM_BIAS  (SM_HALO + 2*HPLANE_B + 32)    // 143,776 (32B zero pad tail)
#define SMEM_BYTES (SM_BIAS + 352)              // 144,128

#define NTHR 512

#define HSZ (Bc*Fc*HWc)
#define XSZ (Bc*Tc*3*HWc)

// ===========================================================================
// Device globals
// ===========================================================================
__device__ __nv_bfloat16 g_B[2*88*BROW];        // packed weights hi/lo
__device__ __nv_bfloat16 g_hh0[HSZ], g_hl0[HSZ];
__device__ __nv_bfloat16 g_hh1[HSZ], g_hl1[HSZ];
__device__ float         g_c[HSZ];
__device__ __nv_bfloat16 g_xh[XSZ], g_xl[XSZ];

// ===========================================================================
// PTX helpers (compute_103-safe: ldmatrix + mma.sync only)
// ===========================================================================
__device__ __forceinline__ uint32_t smem_to_u32(const void* p) {
    uint32_t a;
    asm("{ .reg .u64 t; cvta.to.shared.u64 t, %1; cvt.u32.u64 %0, t; }"
        : "=r"(a) : "l"(p));
    return a;
}
#define LDSM_X4(r0,r1,r2,r3,addr) \
    asm volatile("ldmatrix.sync.aligned.m8n8.x4.shared.b16 {%0,%1,%2,%3}, [%4];" \
        : "=r"(r0),"=r"(r1),"=r"(r2),"=r"(r3) : "r"(addr))
#define LDSM_X2(r0,r1,addr) \
    asm volatile("ldmatrix.sync.aligned.m8n8.x2.shared.b16 {%0,%1}, [%2];" \
        : "=r"(r0),"=r"(r1) : "r"(addr))
#define MMA16816(d,a0,a1,a2,a3,b0,b1) \
    asm volatile("mma.sync.aligned.m16n8k16.row.col.f32.bf16.bf16.f32 " \
        "{%0,%1,%2,%3}, {%4,%5,%6,%7}, {%8,%9}, {%0,%1,%2,%3};" \
        : "+f"((d)[0]),"+f"((d)[1]),"+f"((d)[2]),"+f"((d)[3]) \
        : "r"(a0),"r"(a1),"r"(a2),"r"(a3),"r"(b0),"r"(b1))

__device__ __forceinline__ float hsig(float v) {
    return fminf(fmaxf(0.2f*v + 0.5f, 0.0f), 1.0f);
}

// ===========================================================================
// Aux kernels
// ===========================================================================
__global__ void zero_kernel() {
    for (int i = blockIdx.x*blockDim.x + threadIdx.x; i < HSZ; i += gridDim.x*blockDim.x) {
        g_c[i] = 0.0f;
        g_hh0[i] = __float2bfloat16(0.0f);
        g_hl0[i] = __float2bfloat16(0.0f);
    }
}

// x -> planar bf16 hi/lo: plane ((b*T+t)*3+c), idx [HW]
__global__ void xsplit_kernel(const float* __restrict__ x) {
    for (int i = blockIdx.x*blockDim.x + threadIdx.x; i < XSZ; i += gridDim.x*blockDim.x) {
        int p  = i % HWc;
        int r  = i / HWc;
        int c  = r % 3;
        int bt = r / 3;
        float v = x[((size_t)bt*HWc + p)*3 + c];
        __nv_bfloat16 hi = __float2bfloat16(v);
        g_xh[i] = hi;
        g_xl[i] = __float2bfloat16(v - __bfloat162float(hi));
    }
}

// Pack weights: B[prec][n][k], n = 4*co+g, k = dy*80 + dx*24 + cin
// (k%80 >= 72 and k >= 240 are zero pad; co >= 21 zero)
__global__ void packB_kernel(const float* __restrict__ kern, const float* __restrict__ rkern) {
    int i = blockIdx.x*blockDim.x + threadIdx.x;
    const int TOT = 2*88*BROW;
    if (i >= TOT) return;
    int prec = i / (88*BROW);
    int r    = i - prec*(88*BROW);
    int n    = r / BROW;
    int k    = r - n*BROW;
    int co = n >> 2, g = n & 3;
    float w = 0.0f;
    if (k < 240 && co < Fc) {
        int dy = k / 80, r2 = k - dy*80;
        if (r2 < 72) {
            int dx = r2 / 24, cin = r2 - dx*24;
            int col = g*Fc + co;
            if (cin < 3) w = kern [((dy*3 + dx)*3  + cin    )*F4c + col];
            else         w = rkern[((dy*3 + dx)*Fc + (cin-3))*F4c + col];
        }
    }
    __nv_bfloat16 hi = __float2bfloat16(w);
    g_B[i] = prec ? __float2bfloat16(w - __bfloat162float(hi)) : hi;
}

// ===========================================================================
// One ConvLSTM timestep: bf16x3 HMMA GEMM (M=384, N=88, K=3x240), 16 warps
// ===========================================================================
__global__ __launch_bounds__(NTHR, 1)
void step_kernel(const float* __restrict__ bias, int t) {
    extern __shared__ unsigned char smem[];
    const uint32_t sbase = smem_to_u32(smem);
    const int tid  = threadIdx.x;
    const int w    = tid >> 5;
    const int lane = tid & 31;
    const int b  = blockIdx.z;
    const int x0 = blockIdx.x * TILE_W;
    const int y0 = blockIdx.y * TILE_H;

    const __nv_bfloat16* hh_in = (t & 1) ? g_hh1 : g_hh0;
    const __nv_bfloat16* hl_in = (t & 1) ? g_hl1 : g_hl0;
    __nv_bfloat16* hh_out = (t & 1) ? g_hh0 : g_hh1;
    __nv_bfloat16* hl_out = (t & 1) ? g_hl0 : g_hl1;

    // ---- Stage B (flat copy, pre-packed n-major hi/lo) ----
    {
        const float4* gB = reinterpret_cast<const float4*>(g_B);
        float4* sB = reinterpret_cast<float4*>(smem + SM_B);
        #pragma unroll 4
        for (int i = tid; i < B_TOTAL_B/16; i += NTHR) sB[i] = gB[i];
    }
    // ---- Bias (n = 4co+g) ----
    if (tid < 88) {
        int co = tid >> 2, g = tid & 3;
        reinterpret_cast<float*>(smem + SM_BIAS)[tid] = (co < Fc) ? bias[g*Fc + co] : 0.0f;
    }
    // ---- Halo staging: [prec][r][c][ch] channel-last, 4B (ch-pair) stores ----
    {
        const int HTOT = 2*HROWS*(HCH/2)*HCOLS;   // 14,112 pair-stores
        for (int i = tid; i < HTOT; i += NTHR) {
            int c   = i % HCOLS;
            int chp = (i / HCOLS) % (HCH/2);
            int r   = (i / (HCOLS*(HCH/2))) % HROWS;
            int p   = i / (HCOLS*(HCH/2)*HROWS);
            int gy = y0 + r - 1, gx = x0 + c - 1;
            __nv_bfloat162 v;
            v.x = __float2bfloat16(0.0f); v.y = v.x;
            if ((unsigned)gy < (unsigned)Hc && (unsigned)gx < (unsigned)Wc) {
                size_t pix = (size_t)gy*Wc + gx;
                #pragma unroll
                for (int q = 0; q < 2; q++) {
                    int ch = 2*chp + q;
                    __nv_bfloat16 val;
                    if (ch < 3) {
                        const __nv_bfloat16* pl = (p ? g_xl : g_xh)
                            + ((size_t)((b*Tc + t)*3 + ch))*HWc;
                        val = pl[pix];
                    } else {
                        const __nv_bfloat16* pl = (p ? hl_in : hh_in)
                            + ((size_t)(b*Fc + (ch - 3)))*HWc;
                        val = pl[pix];
                    }
                    if (q == 0) v.x = val; else v.y = val;
                }
            }
            *reinterpret_cast<__nv_bfloat162*>(
                smem + SM_HALO + (size_t)p*HPLANE_B
                + ((size_t)(r*HCOLS + c)*HCH + 2*chp)*2) = v;
        }
        // zero 32B pad tail after plane 1 (A k-pad overreads land here)
        if (tid < 8)
            reinterpret_cast<uint32_t*>(smem + SM_HALO + 2*HPLANE_B)[tid] = 0;
    }
    __syncthreads();

    // ---- Warp tile: 16 warps = 4 rows x 2 mcols x 2 nhalves ----
    const int my    = w >> 2;            // pixel row in tile (0..3)
    const int mxb   = 48*((w >> 1) & 1); // pixel col base (0 or 48)
    const int nhalf = w & 1;             // 0: n 0..47 (nf 6), 1: n 48..87 (nf 5)
    const int NF    = nhalf ? 5 : 6;

    float d[3][6][4];
    #pragma unroll
    for (int mf = 0; mf < 3; mf++)
        #pragma unroll
        for (int nf = 0; nf < 6; nf++)
            #pragma unroll
            for (int q = 0; q < 4; q++) d[mf][nf][q] = 0.0f;

    // ldmatrix lane addressing components
    const uint32_t aLane = (uint32_t)(lane & 15)*48 + (uint32_t)((lane >> 4) & 1)*16;
    const uint32_t bLane = (uint32_t)(lane & 7)*496 + (uint32_t)((lane >> 3) & 1)*16;
    const uint32_t nOff  = (uint32_t)nhalf * (48*496);

    // 3 compensation passes: (Ah,Bh), (Al,Bh), (Ah,Bl)
    #pragma unroll 1
    for (int ps = 0; ps < 3; ps++) {
        const uint32_t Ab = sbase + SM_HALO + ((ps == 1) ? HPLANE_B : 0);
        const uint32_t Bb = sbase + SM_B + ((ps == 2) ? BPLANE_B : 0) + nOff + bLane;
        #pragma unroll 1
        for (int dy = 0; dy < 3; dy++) {
            const uint32_t Arow = Ab + (uint32_t)((my + dy)*HCOLS + mxb)*48 + aLane;
            const uint32_t Brow = Bb + (uint32_t)dy*160;
            #pragma unroll
            for (int c = 0; c < 5; c++) {
                uint32_t bq[12];
                #pragma unroll
                for (int nf = 0; nf < 6; nf++)
                    if (nf < NF)
                        LDSM_X2(bq[2*nf], bq[2*nf+1], Brow + nf*(8*496) + c*32);
                #pragma unroll
                for (int mf = 0; mf < 3; mf++) {
                    uint32_t a0, a1, a2, a3;
                    LDSM_X4(a0, a1, a2, a3, Arow + mf*(16*48) + c*32);
                    #pragma unroll
                    for (int nf = 0; nf < 6; nf++)
                        if (nf < NF)
                            MMA16816(d[mf][nf], a0, a1, a2, a3, bq[2*nf], bq[2*nf+1]);
                }
            }
        }
    }

    // ---- Epilogue: shfl_xor(1) gate exchange, per-lane (pixel, co) update ----
    const int gid    = lane >> 2;
    const int co_off = (lane >> 1) & 1;
    const bool lowrow = ((lane & 1) == 0);
    const int gy = y0 + my;
    const int cob = nhalf * 12;
    const float* sb_all = reinterpret_cast<const float*>(smem + SM_BIAS);

    #pragma unroll
    for (int mf = 0; mf < 3; mf++) {
        #pragma unroll
        for (int nf = 0; nf < 6; nf++) {
            if (nf >= NF) continue;
            float* dd = d[mf][nf];
            float r0 = __shfl_xor_sync(0xFFFFFFFFu, dd[0], 1);
            float r1 = __shfl_xor_sync(0xFFFFFFFFu, dd[1], 1);
            float r2 = __shfl_xor_sync(0xFFFFFFFFu, dd[2], 1);
            float r3 = __shfl_xor_sync(0xFFFFFFFFu, dd[3], 1);
            float zi, zf, zg, zo;
            int rowm;
            if (lowrow) { zi = dd[0]; zf = dd[1]; zg = r0;    zo = r1;    rowm = gid; }
            else        { zi = r2;    zf = r3;    zg = dd[2]; zo = dd[3]; rowm = gid + 8; }
            const int co = cob + 2*nf + co_off;
            const int gx = x0 + mxb + mf*16 + rowm;
            if (co < Fc && gx < Wc && gy < Hc) {
                const float* sb = sb_all + co*4;
                float ig = hsig(zi + sb[0]);
                float fg = hsig(zf + sb[1]);
                float gg = tanhf(zg + sb[2]);
                float og = hsig(zo + sb[3]);
                size_t idx = ((size_t)(b*Fc + co))*HWc + (size_t)gy*Wc + gx;
                float cn = fg * g_c[idx] + ig * gg;
                g_c[idx] = cn;
                float h = og * tanhf(cn);
                __nv_bfloat16 hh = __float2bfloat16(h);
                hh_out[idx] = hh;
                hl_out[idx] = __float2bfloat16(h - __bfloat162float(hh));
            }
        }
    }
}

// ===========================================================================
// out[b,h,w,co] = (h_hi + h_lo)[b,co,h,w] * mask[h,w]
// ===========================================================================
__global__ void mask_out_kernel(const float* __restrict__ mask, float* __restrict__ out) {
    const int n = Bc*HWc*Fc;
    int i = blockIdx.x*blockDim.x + threadIdx.x;
    if (i >= n) return;
    int co   = i % Fc;
    int rest = i / Fc;
    int p    = rest % HWc;
    int b    = rest / HWc;
    size_t idx = ((size_t)(b*Fc + co))*HWc + p;
    float h = __bfloat162float(g_hh0[idx]) + __bfloat162float(g_hl0[idx]);
    out[i] = h * mask[p];
}

// ===========================================================================
extern "C" void kernel_launch(void* const* d_in, const int* in_sizes, int n_in,
                              void* d_out, int out_size) {
    const float* x     = (const float*)d_in[0];
    const float* kern  = (const float*)d_in[1];
    const float* rkern = (const float*)d_in[2];
    const float* bias  = (const float*)d_in[3];
    const float* mask  = (const float*)d_in[4];
    float* out = (float*)d_out;
    (void)in_sizes; (void)n_in; (void)out_size;

    cudaFuncSetAttribute(step_kernel, cudaFuncAttributeMaxDynamicSharedMemorySize,
                         SMEM_BYTES);

    zero_kernel<<<2048, 256>>>();
    xsplit_kernel<<<4096, 256>>>(x);
    packB_kernel<<<(2*88*BROW + 255)/256, 256>>>(kern, rkern);

    dim3 grid((Wc + TILE_W - 1)/TILE_W, (Hc + TILE_H - 1)/TILE_H, Bc); // (2,41,16)
    for (int t = 0; t < Tc; t++) {
        step_kernel<<<grid, NTHR, SMEM_BYTES>>>(bias, t);
    }

    const int n = Bc*HWc*Fc;
    mask_out_kernel<<<(n + 255)/256, 256>>>(mask, out);
}